// round 5
// baseline (speedup 1.0000x reference)
#include <cuda_runtime.h>
#include <math_constants.h>

// Problem constants (fixed shapes for this problem instance)
#define NEWN  65536     // new (coarse) nodes
#define BB    4         // batch
#define VV    64        // feature dim
#define BVN   256       // BB*VV fused columns
#define SPB   32        // segments handled per block
#define SMAXC 1024      // staged col capacity (block nnz range avg ~128)
#define UF    8         // prefetch pipeline depth

// Scratch: segment start offsets (row is sorted, every segment non-empty)
__device__ int g_seg_start[NEWN + 1];

// ---------------------------------------------------------------------------
// Kernel 1: segment boundaries from sorted row[]
// ---------------------------------------------------------------------------
__global__ void build_starts_kernel(const int* __restrict__ row, int nnz) {
    int i = blockIdx.x * blockDim.x + threadIdx.x;
    if (i >= nnz) return;
    int r = row[i];
    if (i == 0) {
        g_seg_start[r] = 0;
    } else if (r != __ldg(row + i - 1)) {
        g_seg_start[r] = i;
    }
    if (i == nnz - 1) g_seg_start[NEWN] = nnz;
}

// ---------------------------------------------------------------------------
// Kernel 2: flattened, software-pipelined per-segment argmax pool.
//
// Thread t owns column j = v*BB + b (b = t>>6, v = t&63): per child node the
// warp's x gather is one contiguous 128B line. The 32 segments of a block are
// scanned as ONE flat loop over the block's nnz range with UF=8 prefetch
// slots, so each warp keeps 8 independent gathers in flight (latency hiding).
// Argmax node ids are staged in smem and emitted transposed with STG.128.
// ---------------------------------------------------------------------------
__global__ __launch_bounds__(256)
void pool_kernel(const float* __restrict__ x,
                 const float* __restrict__ weights,
                 const int*   __restrict__ col,
                 float* __restrict__ out,
                 int oldN,
                 int write_idx) {
    __shared__ int   s_node[BVN * SPB];   // [j][ml] argmax node ids (32 KiB)
    __shared__ int   s_abs[SPB + 2];      // absolute boundaries (+pad, OOB-safe)
    __shared__ float s_w[SPB + 1];        // per-segment weight (+pad)
    __shared__ int   s_col[SMAXC];        // staged col entries for this block

    const int t  = threadIdx.x;
    const int b  = t >> 6;
    const int v  = t & 63;
    const int j  = v * BB + b;
    const int m0 = blockIdx.x * SPB;

    if (t <= SPB) {
        int st = g_seg_start[m0 + t];
        s_abs[t] = st;
        if (t < SPB) s_w[t] = __ldg(weights + st);
    }
    __syncthreads();

    const int Sg = s_abs[0];
    const int L  = s_abs[SPB] - Sg;

    for (int i = t; i < L && i < SMAXC; i += 256)
        s_col[i] = __ldg(col + Sg + i);
    __syncthreads();

    // base pointer for this thread's (b, v) slice of x
    const float* xb = x + (size_t)b * oldN * VV + v;

    // ---- software pipeline: UF independent (node, val) slots in flight ----
    int   pn[UF];
    float pv[UF];
    #pragma unroll
    for (int u = 0; u < UF; ++u) { pn[u] = 0; pv[u] = 0.f; }

    #pragma unroll
    for (int u = 0; u < UF; ++u) {
        if (u < L) {
            int n = (u < SMAXC) ? s_col[u] : __ldg(col + Sg + u);
            pn[u] = n;
            pv[u] = __ldg(xb + ((size_t)n << 6));   // node*VV
        }
    }

    int   ml        = 0;
    int   cur_end   = s_abs[1] - Sg;
    float w         = s_w[0];
    float best_wv   = -CUDART_INF_F;
    float best_val  = 0.0f;
    int   best_node = 0;

    for (int base = 0; base < L; base += UF) {
        #pragma unroll
        for (int u = 0; u < UF; ++u) {
            const int i = base + u;
            if (i < L) {
                const int   node = pn[u];
                const float val  = pv[u];

                // prefetch slot u for iteration i+UF (issued before consume)
                const int ip = i + UF;
                if (ip < L) {
                    int n2 = (ip < SMAXC) ? s_col[ip] : __ldg(col + Sg + ip);
                    pn[u] = n2;
                    pv[u] = __ldg(xb + ((size_t)n2 << 6));
                }

                const float wv = w * val;            // matches reference fp32 mul
                if (wv > best_wv) {                  // strict > == min-index tiebreak
                    best_wv = wv; best_val = val; best_node = node;
                }

                if (i + 1 == cur_end) {              // segment boundary: flush
                    const int m = m0 + ml;
                    // x_pooled[b, m, v] -- 128B coalesced per warp
                    out[((size_t)b * NEWN + m) * VV + v] = best_val;
                    s_node[j * SPB + ml] = best_node;
                    ++ml;
                    cur_end = s_abs[ml + 1] - Sg;    // padded: safe at ml==SPB
                    w       = s_w[ml];               // padded: safe at ml==SPB
                    best_wv = -CUDART_INF_F; best_val = 0.0f; best_node = 0;
                }
            }
        }
    }

    if (!write_idx) return;                          // uniform across block
    __syncthreads();

    // nnz_ind[0] at out1[j*NEWN + m], nnz_ind[1] = j at out2[same].
    // Vectorized STG.128: per warp, 8 lanes cover 32 consecutive m per jj.
    float* out1 = out  + (size_t)BB  * NEWN * VV;    // +16,777,216
    float* out2 = out1 + (size_t)BVN * NEWN;         // +16,777,216

    const int jj_lo = t >> 3;                        // 0..31
    const int mlb   = (t & 7) * 4;                   // 4-segment chunk
    #pragma unroll
    for (int it = 0; it < 8; ++it) {
        const int jj = it * 32 + jj_lo;
        const int4 n4 = *(const int4*)&s_node[jj * SPB + mlb];
        const float4 f4 = make_float4((float)n4.x, (float)n4.y,
                                      (float)n4.z, (float)n4.w);
        const size_t off = (size_t)jj * NEWN + m0 + mlb;
        *(float4*)&out1[off] = f4;                   // exact: node < 2^24
        const float fj = (float)jj;
        *(float4*)&out2[off] = make_float4(fj, fj, fj, fj);
    }
}

// ---------------------------------------------------------------------------
// Launch
// inputs (metadata order): x f32[B,OLD,V], weights f32[nnz], row i32[nnz],
//                          col i32[nnz], new_nodes i32[1]
// output: concat(x_pooled f32[B,NEWN,V], nnz_ind[2, BV*NEWN])
// ---------------------------------------------------------------------------
extern "C" void kernel_launch(void* const* d_in, const int* in_sizes, int n_in,
                              void* d_out, int out_size) {
    const float* x       = (const float*)d_in[0];
    const float* weights = (const float*)d_in[1];
    const int*   row     = (const int*)d_in[2];
    const int*   col     = (const int*)d_in[3];

    const int nnz  = in_sizes[3];
    const int oldN = in_sizes[0] / (BB * VV);

    build_starts_kernel<<<(nnz + 255) / 256, 256>>>(row, nnz);

    const int pooled_elems = BB * NEWN * VV;                 // 16,777,216
    const int write_idx    = (out_size >= 3 * pooled_elems) ? 1 : 0;

    pool_kernel<<<NEWN / SPB, 256>>>(x, weights, col, (float*)d_out,
                                     oldN, write_idx);
}

// round 6
// speedup vs baseline: 2.1321x; 2.1321x over previous
#include <cuda_runtime.h>
#include <math_constants.h>

// Problem constants (fixed shapes for this problem instance)
#define NEWN 65536      // new (coarse) nodes
#define BB   4          // batch
#define VV   64         // feature dim
#define BVN  256        // BB*VV fused columns
#define SPB  32         // segments handled per block
#define SPG  8          // segments per 64-thread group (SPB/4)

// Scratch: segment start offsets (row is sorted, every segment non-empty)
__device__ int g_seg_start[NEWN + 1];

// ---------------------------------------------------------------------------
// Kernel 1: segment boundaries from sorted row[]
// ---------------------------------------------------------------------------
__global__ void build_starts_kernel(const int* __restrict__ row, int nnz) {
    int i = blockIdx.x * blockDim.x + threadIdx.x;
    if (i >= nnz) return;
    int r = row[i];
    if (i == 0) {
        g_seg_start[r] = 0;
    } else if (r != __ldg(row + i - 1)) {
        g_seg_start[r] = i;
    }
    if (i == nnz - 1) g_seg_start[NEWN] = nnz;
}

// Bank-swizzled staging index for argmax node ids.
// j>>4 == v-group id; rotating ml by it spreads the 16-lane column stride
// across banks (2-way conflict instead of 16-way).
__device__ __forceinline__ int node_idx(int j, int ml) {
    return j * SPB + ((ml + (j >> 4)) & (SPB - 1));
}

// ---------------------------------------------------------------------------
// Kernel 2: per-segment weighted argmax pool, float4-vectorized gathers.
//
// 256 threads = 4 groups of 64. Group g owns segments [8g, 8g+8) of the
// block's 32. Within a group: b = tg>>4 (batch), vg = tg&15, v = 4*vg.
// Each thread gathers x[b, node, v..v+3] as one LDG.128 (warp = 512B per
// gather instruction -> 4x the in-flight bytes of the scalar version) and
// tracks 4 independent per-column argmaxes. Loop structure is the simple
// per-segment scan (proven fastest); ptxas batches the independent loads.
// ---------------------------------------------------------------------------
__global__ __launch_bounds__(256)
void pool_kernel(const float* __restrict__ x,
                 const float* __restrict__ weights,
                 const int*   __restrict__ col,
                 float* __restrict__ out,
                 int oldN,
                 int write_idx) {
    __shared__ int   s_node[BVN * SPB];   // swizzled [j][ml] argmax nodes (32 KiB)
    __shared__ int   s_abs[SPB + 1];
    __shared__ float s_w[SPB];

    const int t  = threadIdx.x;
    const int g  = t >> 6;                // segment subgroup 0..3
    const int tg = t & 63;
    const int b  = tg >> 4;               // batch 0..3
    const int vg = tg & 15;               // feature group 0..15
    const int v  = vg << 2;               // feature base 0..60
    const int m0 = blockIdx.x * SPB;

    if (t <= SPB) {
        int st = g_seg_start[m0 + t];
        s_abs[t] = st;
        if (t < SPB) s_w[t] = __ldg(weights + st);
    }
    __syncthreads();

    // this thread's (b, v) float4 slice of x
    const float4* xb =
        (const float4*)(x + (size_t)b * oldN * VV + v);

    #pragma unroll
    for (int ml = g * SPG; ml < g * SPG + SPG; ++ml) {
        const int   s = s_abs[ml];
        const int   e = s_abs[ml + 1];
        const float w = s_w[ml];

        float4 bwv = make_float4(-CUDART_INF_F, -CUDART_INF_F,
                                 -CUDART_INF_F, -CUDART_INF_F);
        float4 bval = make_float4(0.f, 0.f, 0.f, 0.f);
        int bn0 = 0, bn1 = 0, bn2 = 0, bn3 = 0;

        for (int i = s; i < e; ++i) {
            const int    node = __ldg(col + i);         // group-uniform, L1 hit
            const float4 val  = __ldg(xb + node * (VV / 4));  // LDG.128, coalesced
            // fp32 mul + strict > scan == reference segment_max + min-index tiebreak
            float wv;
            wv = w * val.x; if (wv > bwv.x) { bwv.x = wv; bval.x = val.x; bn0 = node; }
            wv = w * val.y; if (wv > bwv.y) { bwv.y = wv; bval.y = val.y; bn1 = node; }
            wv = w * val.z; if (wv > bwv.z) { bwv.z = wv; bval.z = val.z; bn2 = node; }
            wv = w * val.w; if (wv > bwv.w) { bwv.w = wv; bval.w = val.w; bn3 = node; }
        }

        const int m = m0 + ml;
        // x_pooled[b, m, v..v+3] -- STG.128, coalesced per half-warp
        *(float4*)&out[((size_t)b * NEWN + m) * VV + v] = bval;

        // stage argmax nodes (column j = (v+k)*BB + b), bank-swizzled
        s_node[node_idx((v + 0) * BB + b, ml)] = bn0;
        s_node[node_idx((v + 1) * BB + b, ml)] = bn1;
        s_node[node_idx((v + 2) * BB + b, ml)] = bn2;
        s_node[node_idx((v + 3) * BB + b, ml)] = bn3;
    }

    __syncthreads();
    if (!write_idx) return;                 // uniform across block

    // nnz_ind[0] at out1[j*NEWN + m], nnz_ind[1] = j at out2[same offset].
    // Per thread: one jj per pass, 4 consecutive m -> STG.128.
    float* out1 = out  + (size_t)BB  * NEWN * VV;   // +16,777,216
    float* out2 = out1 + (size_t)BVN * NEWN;        // +16,777,216

    const int jl  = t >> 3;                 // 0..31
    const int mlb = (t & 7) * 4;            // segment chunk base
    #pragma unroll
    for (int it = 0; it < 8; ++it) {
        const int jj = it * 32 + jl;
        float4 f;
        f.x = (float)s_node[node_idx(jj, mlb + 0)];
        f.y = (float)s_node[node_idx(jj, mlb + 1)];
        f.z = (float)s_node[node_idx(jj, mlb + 2)];
        f.w = (float)s_node[node_idx(jj, mlb + 3)];
        const size_t off = (size_t)jj * NEWN + m0 + mlb;
        *(float4*)&out1[off] = f;           // exact: node < 2^24
        const float fj = (float)jj;
        *(float4*)&out2[off] = make_float4(fj, fj, fj, fj);
    }
}

// ---------------------------------------------------------------------------
// Launch
// inputs (metadata order): x f32[B,OLD,V], weights f32[nnz], row i32[nnz],
//                          col i32[nnz], new_nodes i32[1]
// output: concat(x_pooled f32[B,NEWN,V], nnz_ind[2, BV*NEWN])
// ---------------------------------------------------------------------------
extern "C" void kernel_launch(void* const* d_in, const int* in_sizes, int n_in,
                              void* d_out, int out_size) {
    const float* x       = (const float*)d_in[0];
    const float* weights = (const float*)d_in[1];
    const int*   row     = (const int*)d_in[2];
    const int*   col     = (const int*)d_in[3];

    const int nnz  = in_sizes[3];
    const int oldN = in_sizes[0] / (BB * VV);

    build_starts_kernel<<<(nnz + 255) / 256, 256>>>(row, nnz);

    const int pooled_elems = BB * NEWN * VV;                 // 16,777,216
    const int write_idx    = (out_size >= 3 * pooled_elems) ? 1 : 0;

    pool_kernel<<<NEWN / SPB, 256>>>(x, weights, col, (float*)d_out,
                                     oldN, write_idx);
}